// round 2
// baseline (speedup 1.0000x reference)
#include <cuda_runtime.h>
#include <cuda_bf16.h>

// DistMult decoder:
//   out[e] = sigmoid( sum_d x[left[e],d] * R[type[e],d] * x[right[e],d] )
//
// Inputs identified by element count (robust to ordering):
//   x          float32 [100000, 32]  -> 3,200,000 elems
//   R          float32 [964, 32]     ->    30,848 elems
//   edge_index int     [2, E]        ->       2*E elems   (E = out_size)
//   edge_type  int     [E]           ->         E elems
// Index dtype (int32 vs int64) is detected on-device by a probe kernel.
//
// 8 lanes cooperate on one edge; each lane loads one float4 of the 128-B
// rows xl/xr/rel -> each warp LDG.128 touches only 4 distinct lines.
// Reduce across 8 lanes via shfl_xor (4,2,1).

__device__ int g_idx_is64;

__global__ void detect_idx_dtype(const void* edge_index_raw)
{
    // Genuine int64 node indices are < 100000. int32 data reinterpreted as
    // int64 packs two random ids -> value >= 2^32 with prob 1-1e-5 each.
    const long long* p = (const long long*)edge_index_raw;
    int is64 = 1;
    #pragma unroll
    for (int i = 0; i < 8; i++) {
        long long v = p[i];
        if (v < 0 || v >= 100000LL) is64 = 0;
    }
    g_idx_is64 = is64;
}

__global__ void __launch_bounds__(256) distmult_kernel(
    const float* __restrict__ x,
    const float* __restrict__ R,
    const void* __restrict__ edge_index_raw,
    const void* __restrict__ edge_type_raw,
    float* __restrict__ out,
    int E)
{
    int tid  = blockIdx.x * blockDim.x + threadIdx.x;
    int edge = tid >> 3;          // 8 lanes per edge
    int lane = tid & 7;
    if (edge >= E) return;

    long long l, r, t;
    if (g_idx_is64) {
        const long long* ei = (const long long*)edge_index_raw;
        const long long* et = (const long long*)edge_type_raw;
        l = __ldg(ei + edge);
        r = __ldg(ei + (long long)E + edge);
        t = __ldg(et + edge);
    } else {
        const int* ei = (const int*)edge_index_raw;
        const int* et = (const int*)edge_type_raw;
        l = __ldg(ei + edge);
        r = __ldg(ei + E + edge);
        t = __ldg(et + edge);
    }

    const float4* xl4 = reinterpret_cast<const float4*>(x + l * 32);
    const float4* xr4 = reinterpret_cast<const float4*>(x + r * 32);
    const float4* rl4 = reinterpret_cast<const float4*>(R + t * 32);

    float4 a = __ldg(xl4 + lane);
    float4 b = __ldg(xr4 + lane);
    float4 c = __ldg(rl4 + lane);   // warp-near-uniform (sorted types)

    float s = a.x * c.x * b.x
            + a.y * c.y * b.y
            + a.z * c.z * b.z
            + a.w * c.w * b.w;

    s += __shfl_xor_sync(0xffffffffu, s, 4);
    s += __shfl_xor_sync(0xffffffffu, s, 2);
    s += __shfl_xor_sync(0xffffffffu, s, 1);

    if (lane == 0) {
        out[edge] = 1.0f / (1.0f + __expf(-s));
    }
}

extern "C" void kernel_launch(void* const* d_in, const int* in_sizes, int n_in,
                              void* d_out, int out_size)
{
    int E = out_size;  // one score per edge

    // Identify inputs by element count (robust to metadata ordering).
    const float* x  = nullptr;
    const float* R  = nullptr;
    const void*  ei = nullptr;
    const void*  et = nullptr;
    for (int i = 0; i < n_in; i++) {
        long long sz = in_sizes[i];
        if      (sz == 2LL * E)               ei = d_in[i];
        else if (sz == (long long)E)          et = d_in[i];
        else if (sz == 30848LL)               R  = (const float*)d_in[i];
        else                                  x  = (const float*)d_in[i];
    }
    // Fallback to canonical order if anything is ambiguous/missing.
    if (!x || !R || !ei || !et) {
        x  = (const float*)d_in[0];
        R  = (const float*)d_in[1];
        ei = d_in[2];
        et = d_in[3];
    }

    detect_idx_dtype<<<1, 1>>>(ei);

    long long total_threads = (long long)E * 8;
    int block = 256;
    long long grid = (total_threads + block - 1) / block;

    distmult_kernel<<<(unsigned int)grid, block>>>(
        x, R, ei, et, (float*)d_out, E);
}

// round 3
// speedup vs baseline: 1.3063x; 1.3063x over previous
#include <cuda_runtime.h>
#include <cuda_bf16.h>

// DistMult decoder:
//   out[e] = sigmoid( sum_d x[left[e],d] * R[type[e],d] * x[right[e],d] )
//
// Inputs identified by element count (robust to ordering):
//   x          float32 [100000, 32]  -> 3,200,000 elems
//   R          float32 [964, 32]     ->    30,848 elems
//   edge_index int     [2, E]        ->       2*E elems   (E = out_size)
//   edge_type  int     [E]           ->         E elems
// Index dtype (int32 vs int64) detected on-device by a probe kernel.
//
// R3 structure:
//  - 64 edges per 256-thread block; indices smem-staged once (int32).
//  - 8 lanes per edge (full 128B line per LDG inst), 2 edges per group
//    for MLP=6 row loads in flight per thread.
//  - All address math 32-bit; OOB edges staged as index 0 (loads legal,
//    store guarded).

__device__ int g_idx_is64;

__global__ void detect_idx_dtype(const void* edge_index_raw)
{
    const long long* p = (const long long*)edge_index_raw;
    int is64 = 1;
    #pragma unroll
    for (int i = 0; i < 8; i++) {
        long long v = p[i];
        if (v < 0 || v >= 100000LL) is64 = 0;
    }
    g_idx_is64 = is64;
}

__device__ __forceinline__ float dot8(float4 a0, float4 a1,
                                      float4 c0, float4 c1,
                                      float4 b0, float4 b1)
{
    float s;
    s = (a0.x * c0.x) * b0.x;
    s = fmaf(a0.y * c0.y, b0.y, s);
    s = fmaf(a0.z * c0.z, b0.z, s);
    s = fmaf(a0.w * c0.w, b0.w, s);
    s = fmaf(a1.x * c1.x, b1.x, s);
    s = fmaf(a1.y * c1.y, b1.y, s);
    s = fmaf(a1.z * c1.z, b1.z, s);
    s = fmaf(a1.w * c1.w, b1.w, s);
    return s;
}

__global__ void __launch_bounds__(256) distmult_kernel(
    const float* __restrict__ x,
    const float* __restrict__ R,
    const void* __restrict__ edge_index_raw,
    const void* __restrict__ edge_type_raw,
    float* __restrict__ out,
    int E)
{
    __shared__ int s_l[64];
    __shared__ int s_r[64];
    __shared__ int s_t[64];

    const int e0  = blockIdx.x * 64;
    const int tid = threadIdx.x;

    // ---- Stage 192 indices (l, r, t for 64 edges), convert to int32 ----
    if (tid < 192) {
        int slot = tid & 63;     // edge within block
        int seg  = tid >> 6;     // 0 = left, 1 = right, 2 = type
        int e    = e0 + slot;
        int v    = 0;            // OOB edges -> row 0 (legal loads)
        if (e < E) {
            if (g_idx_is64) {
                const long long* ei = (const long long*)edge_index_raw;
                const long long* et = (const long long*)edge_type_raw;
                if      (seg == 0) v = (int)__ldg(ei + e);
                else if (seg == 1) v = (int)__ldg(ei + E + e);
                else               v = (int)__ldg(et + e);
            } else {
                const int* ei = (const int*)edge_index_raw;
                const int* et = (const int*)edge_type_raw;
                if      (seg == 0) v = __ldg(ei + e);
                else if (seg == 1) v = __ldg(ei + E + e);
                else               v = __ldg(et + e);
            }
        }
        if      (seg == 0) s_l[slot] = v;
        else if (seg == 1) s_r[slot] = v;
        else               s_t[slot] = v;
    }
    __syncthreads();

    // ---- Each 8-lane group handles 2 edges ----
    const int gid = tid >> 3;        // 0..31
    const int sub = tid & 7;         // lane within group
    const int ga  = gid * 2;
    const int gb  = ga + 1;

    const int la = s_l[ga], ra = s_r[ga], ta = s_t[ga];
    const int lb = s_l[gb], rb = s_r[gb], tb = s_t[gb];

    // Row pointers; 8 lanes x float4 = one 128B line per instruction.
    const float4* Aa = (const float4*)(x + la * 32) + sub;
    const float4* Ba = (const float4*)(x + ra * 32) + sub;
    const float4* Ca = (const float4*)(R + ta * 32) + sub;
    const float4* Ab = (const float4*)(x + lb * 32) + sub;
    const float4* Bb = (const float4*)(x + rb * 32) + sub;
    const float4* Cb = (const float4*)(R + tb * 32) + sub;

    // 6 independent loads in flight
    float4 a0 = __ldg(Aa);
    float4 b0 = __ldg(Ba);
    float4 c0 = __ldg(Ca);
    float4 a1 = __ldg(Ab);
    float4 b1 = __ldg(Bb);
    float4 c1 = __ldg(Cb);

    float sa;
    sa = (a0.x * c0.x) * b0.x;
    sa = fmaf(a0.y * c0.y, b0.y, sa);
    sa = fmaf(a0.z * c0.z, b0.z, sa);
    sa = fmaf(a0.w * c0.w, b0.w, sa);

    float sb;
    sb = (a1.x * c1.x) * b1.x;
    sb = fmaf(a1.y * c1.y, b1.y, sb);
    sb = fmaf(a1.z * c1.z, b1.z, sb);
    sb = fmaf(a1.w * c1.w, b1.w, sb);

    // Butterfly over the 8 lanes; two independent chains interleave.
    sa += __shfl_xor_sync(0xffffffffu, sa, 4);
    sb += __shfl_xor_sync(0xffffffffu, sb, 4);
    sa += __shfl_xor_sync(0xffffffffu, sa, 2);
    sb += __shfl_xor_sync(0xffffffffu, sb, 2);
    sa += __shfl_xor_sync(0xffffffffu, sa, 1);
    sb += __shfl_xor_sync(0xffffffffu, sb, 1);

    const int ea = e0 + ga;
    const int eb = e0 + gb;
    if (sub == 0 && ea < E) out[ea] = 1.0f / (1.0f + __expf(-sa));
    if (sub == 1 && eb < E) out[eb] = 1.0f / (1.0f + __expf(-sb));
}

extern "C" void kernel_launch(void* const* d_in, const int* in_sizes, int n_in,
                              void* d_out, int out_size)
{
    int E = out_size;  // one score per edge

    const float* x  = nullptr;
    const float* R  = nullptr;
    const void*  ei = nullptr;
    const void*  et = nullptr;
    for (int i = 0; i < n_in; i++) {
        long long sz = in_sizes[i];
        if      (sz == 2LL * E)      ei = d_in[i];
        else if (sz == (long long)E) et = d_in[i];
        else if (sz == 30848LL)      R  = (const float*)d_in[i];
        else                         x  = (const float*)d_in[i];
    }
    if (!x || !R || !ei || !et) {
        x  = (const float*)d_in[0];
        R  = (const float*)d_in[1];
        ei = d_in[2];
        et = d_in[3];
    }

    detect_idx_dtype<<<1, 1>>>(ei);

    int blocks = (E + 63) / 64;
    distmult_kernel<<<blocks, 256>>>(x, R, ei, et, (float*)d_out, E);
}

// round 4
// speedup vs baseline: 1.4775x; 1.1310x over previous
#include <cuda_runtime.h>
#include <cuda_bf16.h>

// DistMult decoder:
//   out[e] = sigmoid( sum_d x[left[e],d] * R[type[e],d] * x[right[e],d] )
//
// R4: 8-lane groups handle 4 edges each (MLP=12 row loads in flight),
// packed f32x2 FMA (FFMA2) for the triple product, sigmoid computed once
// per stored edge, smem-staged int32 indices, 128 edges / 256-thread block.

__device__ int g_idx_is64;

__global__ void detect_idx_dtype(const void* edge_index_raw)
{
    const long long* p = (const long long*)edge_index_raw;
    int is64 = 1;
    #pragma unroll
    for (int i = 0; i < 8; i++) {
        long long v = p[i];
        if (v < 0 || v >= 100000LL) is64 = 0;
    }
    g_idx_is64 = is64;
}

#define PACK2(out_, x_, y_) \
    asm("mov.b64 %0, {%1, %2};" : "=l"(out_) : "f"(x_), "f"(y_))
#define UNPACK2(x_, y_, in_) \
    asm("mov.b64 {%0, %1}, %2;" : "=f"(x_), "=f"(y_) : "l"(in_))
#define MUL2(out_, a_, b_) \
    asm("mul.rn.f32x2 %0, %1, %2;" : "=l"(out_) : "l"(a_), "l"(b_))
#define FMA2(out_, a_, b_, c_) \
    asm("fma.rn.f32x2 %0, %1, %2, %3;" : "=l"(out_) : "l"(a_), "l"(b_), "l"(c_))

// Triple-product partial for one edge on this lane: sum of 4 dims.
__device__ __forceinline__ float triple4(float4 a, float4 c, float4 b)
{
    unsigned long long a0, a1, b0, b1, c0, c1, t, acc;
    PACK2(a0, a.x, a.y); PACK2(a1, a.z, a.w);
    PACK2(b0, b.x, b.y); PACK2(b1, b.z, b.w);
    PACK2(c0, c.x, c.y); PACK2(c1, c.z, c.w);
    MUL2(t, a0, c0);
    MUL2(acc, t, b0);            // acc = a0*c0*b0
    MUL2(t, a1, c1);
    FMA2(acc, t, b1, acc);       // acc += a1*c1*b1
    float lo, hi;
    UNPACK2(lo, hi, acc);
    return lo + hi;
}

__global__ void __launch_bounds__(256) distmult_kernel(
    const float* __restrict__ x,
    const float* __restrict__ R,
    const void* __restrict__ edge_index_raw,
    const void* __restrict__ edge_type_raw,
    float* __restrict__ out,
    int E)
{
    __shared__ int s_l[128];
    __shared__ int s_r[128];
    __shared__ int s_t[128];

    const int e0  = blockIdx.x * 128;
    const int tid = threadIdx.x;

    // ---- Stage 384 indices (l, r, t for 128 edges) as int32 ----
    const int is64 = g_idx_is64;
    #pragma unroll
    for (int i = tid; i < 384; i += 256) {
        int seg  = i >> 7;        // 0 = left, 1 = right, 2 = type
        int slot = i & 127;
        int e    = e0 + slot;
        int v    = 0;             // OOB -> row 0 (legal loads)
        if (e < E) {
            if (is64) {
                const long long* ei = (const long long*)edge_index_raw;
                const long long* et = (const long long*)edge_type_raw;
                if      (seg == 0) v = (int)__ldg(ei + e);
                else if (seg == 1) v = (int)__ldg(ei + E + e);
                else               v = (int)__ldg(et + e);
            } else {
                const int* ei = (const int*)edge_index_raw;
                const int* et = (const int*)edge_type_raw;
                if      (seg == 0) v = __ldg(ei + e);
                else if (seg == 1) v = __ldg(ei + E + e);
                else               v = __ldg(et + e);
            }
        }
        if      (seg == 0) s_l[slot] = v;
        else if (seg == 1) s_r[slot] = v;
        else               s_t[slot] = v;
    }
    __syncthreads();

    // ---- Each 8-lane group handles 4 consecutive edges ----
    const int gid = tid >> 3;        // 0..31
    const int sub = tid & 7;
    const int eb  = gid * 4;         // first edge slot of this group

    const int l0 = s_l[eb+0], r0 = s_r[eb+0], t0 = s_t[eb+0];
    const int l1 = s_l[eb+1], r1 = s_r[eb+1], t1 = s_t[eb+1];
    const int l2 = s_l[eb+2], r2 = s_r[eb+2], t2 = s_t[eb+2];
    const int l3 = s_l[eb+3], r3 = s_r[eb+3], t3 = s_t[eb+3];

    const float4* xb = (const float4*)x;
    const float4* Rb = (const float4*)R;

    // 12 independent row loads in flight (8 lanes x 16 B = one 128 B line each)
    float4 A0 = __ldg(xb + l0 * 8 + sub);
    float4 B0 = __ldg(xb + r0 * 8 + sub);
    float4 A1 = __ldg(xb + l1 * 8 + sub);
    float4 B1 = __ldg(xb + r1 * 8 + sub);
    float4 A2 = __ldg(xb + l2 * 8 + sub);
    float4 B2 = __ldg(xb + r2 * 8 + sub);
    float4 A3 = __ldg(xb + l3 * 8 + sub);
    float4 B3 = __ldg(xb + r3 * 8 + sub);
    float4 C0 = __ldg(Rb + t0 * 8 + sub);   // near-uniform (sorted types)
    float4 C1 = __ldg(Rb + t1 * 8 + sub);
    float4 C2 = __ldg(Rb + t2 * 8 + sub);
    float4 C3 = __ldg(Rb + t3 * 8 + sub);

    float s0 = triple4(A0, C0, B0);
    float s1 = triple4(A1, C1, B1);
    float s2 = triple4(A2, C2, B2);
    float s3 = triple4(A3, C3, B3);

    // Butterfly reduce over the 8 lanes; 4 independent chains interleave.
    s0 += __shfl_xor_sync(0xffffffffu, s0, 4);
    s1 += __shfl_xor_sync(0xffffffffu, s1, 4);
    s2 += __shfl_xor_sync(0xffffffffu, s2, 4);
    s3 += __shfl_xor_sync(0xffffffffu, s3, 4);
    s0 += __shfl_xor_sync(0xffffffffu, s0, 2);
    s1 += __shfl_xor_sync(0xffffffffu, s1, 2);
    s2 += __shfl_xor_sync(0xffffffffu, s2, 2);
    s3 += __shfl_xor_sync(0xffffffffu, s3, 2);
    s0 += __shfl_xor_sync(0xffffffffu, s0, 1);
    s1 += __shfl_xor_sync(0xffffffffu, s1, 1);
    s2 += __shfl_xor_sync(0xffffffffu, s2, 1);
    s3 += __shfl_xor_sync(0xffffffffu, s3, 1);

    // Lanes 0..3 of each group store edges eb+0..eb+3.
    float v = s0;
    if (sub == 1) v = s1;
    if (sub == 2) v = s2;
    if (sub == 3) v = s3;

    const int e = e0 + eb + sub;
    if (sub < 4 && e < E) {
        out[e] = 1.0f / (1.0f + __expf(-v));
    }
}

extern "C" void kernel_launch(void* const* d_in, const int* in_sizes, int n_in,
                              void* d_out, int out_size)
{
    int E = out_size;  // one score per edge

    const float* x  = nullptr;
    const float* R  = nullptr;
    const void*  ei = nullptr;
    const void*  et = nullptr;
    for (int i = 0; i < n_in; i++) {
        long long sz = in_sizes[i];
        if      (sz == 2LL * E)      ei = d_in[i];
        else if (sz == (long long)E) et = d_in[i];
        else if (sz == 30848LL)      R  = (const float*)d_in[i];
        else                         x  = (const float*)d_in[i];
    }
    if (!x || !R || !ei || !et) {
        x  = (const float*)d_in[0];
        R  = (const float*)d_in[1];
        ei = d_in[2];
        et = d_in[3];
    }

    detect_idx_dtype<<<1, 1>>>(ei);

    int blocks = (E + 127) / 128;
    distmult_kernel<<<blocks, 256>>>(x, R, ei, et, (float*)d_out, E);
}

// round 7
// speedup vs baseline: 1.5569x; 1.0537x over previous
#include <cuda_runtime.h>
#include <cuda_bf16.h>

// DistMult decoder:
//   out[e] = sigmoid( sum_d x[left[e],d] * R[type[e],d] * x[right[e],d] )
//
// R5: as R4 (8 lanes/edge, 4 edges/group, f32x2 packed FMA, 128 edges/block)
// plus: __launch_bounds__(256,8) to force 32 regs -> 100% occupancy,
// int4-packed smem index staging (LDS.128), __fdividef sigmoid.

__device__ int g_idx_is64;

__global__ void detect_idx_dtype(const void* edge_index_raw)
{
    const long long* p = (const long long*)edge_index_raw;
    int is64 = 1;
    #pragma unroll
    for (int i = 0; i < 8; i++) {
        long long v = p[i];
        if (v < 0 || v >= 100000LL) is64 = 0;
    }
    g_idx_is64 = is64;
}

#define PACK2(out_, x_, y_) \
    asm("mov.b64 %0, {%1, %2};" : "=l"(out_) : "f"(x_), "f"(y_))
#define UNPACK2(x_, y_, in_) \
    asm("mov.b64 {%0, %1}, %2;" : "=f"(x_), "=f"(y_) : "l"(in_))
#define MUL2(out_, a_, b_) \
    asm("mul.rn.f32x2 %0, %1, %2;" : "=l"(out_) : "l"(a_), "l"(b_))
#define FMA2(out_, a_, b_, c_) \
    asm("fma.rn.f32x2 %0, %1, %2, %3;" : "=l"(out_) : "l"(a_), "l"(b_), "l"(c_))

// Triple-product partial for one edge on this lane: sum over 4 dims.
__device__ __forceinline__ float triple4(float4 a, float4 c, float4 b)
{
    unsigned long long a0, a1, b0, b1, c0, c1, t, acc;
    PACK2(a0, a.x, a.y); PACK2(a1, a.z, a.w);
    PACK2(b0, b.x, b.y); PACK2(b1, b.z, b.w);
    PACK2(c0, c.x, c.y); PACK2(c1, c.z, c.w);
    MUL2(t, a0, c0);
    MUL2(acc, t, b0);            // acc = a0*c0*b0
    MUL2(t, a1, c1);
    FMA2(acc, t, b1, acc);       // acc += a1*c1*b1
    float lo, hi;
    UNPACK2(lo, hi, acc);
    return lo + hi;
}

__global__ void __launch_bounds__(256, 8) distmult_kernel(
    const float* __restrict__ x,
    const float* __restrict__ R,
    const void* __restrict__ edge_index_raw,
    const void* __restrict__ edge_type_raw,
    float* __restrict__ out,
    int E)
{
    __shared__ int4 s_idx[128];   // (l, r, t, 0) per edge

    const int e0  = blockIdx.x * 128;
    const int tid = threadIdx.x;

    // ---- Stage indices for 128 edges as packed int4 ----
    if (tid < 128) {
        int e = e0 + tid;
        int l = 0, r = 0, t = 0;          // OOB -> row 0 (legal loads)
        if (e < E) {
            if (g_idx_is64) {
                const long long* ei = (const long long*)edge_index_raw;
                const long long* et = (const long long*)edge_type_raw;
                l = (int)__ldg(ei + e);
                r = (int)__ldg(ei + E + e);
                t = (int)__ldg(et + e);
            } else {
                const int* ei = (const int*)edge_index_raw;
                const int* et = (const int*)edge_type_raw;
                l = __ldg(ei + e);
                r = __ldg(ei + E + e);
                t = __ldg(et + e);
            }
        }
        s_idx[tid] = make_int4(l, r, t, 0);
    }
    __syncthreads();

    // ---- Each 8-lane group handles 4 consecutive edges ----
    const int gid = tid >> 3;        // 0..31
    const int sub = tid & 7;
    const int eb  = gid * 4;

    // LDS.128 per edge; broadcast within group, conflict-free across groups.
    const int4 i0 = s_idx[eb + 0];
    const int4 i1 = s_idx[eb + 1];
    const int4 i2 = s_idx[eb + 2];
    const int4 i3 = s_idx[eb + 3];

    const float4* xb = (const float4*)x;
    const float4* Rb = (const float4*)R;

    // 12 independent row loads (8 lanes x 16 B = one 128 B line per inst)
    float4 A0 = __ldg(xb + i0.x * 8 + sub);
    float4 B0 = __ldg(xb + i0.y * 8 + sub);
    float4 A1 = __ldg(xb + i1.x * 8 + sub);
    float4 B1 = __ldg(xb + i1.y * 8 + sub);
    float4 A2 = __ldg(xb + i2.x * 8 + sub);
    float4 B2 = __ldg(xb + i2.y * 8 + sub);
    float4 A3 = __ldg(xb + i3.x * 8 + sub);
    float4 B3 = __ldg(xb + i3.y * 8 + sub);
    float4 C0 = __ldg(Rb + i0.z * 8 + sub);   // near-uniform (sorted types)
    float4 C1 = __ldg(Rb + i1.z * 8 + sub);
    float4 C2 = __ldg(Rb + i2.z * 8 + sub);
    float4 C3 = __ldg(Rb + i3.z * 8 + sub);

    float s0 = triple4(A0, C0, B0);
    float s1 = triple4(A1, C1, B1);
    float s2 = triple4(A2, C2, B2);
    float s3 = triple4(A3, C3, B3);

    // Butterfly reduce over 8 lanes; 4 independent chains interleave.
    s0 += __shfl_xor_sync(0xffffffffu, s0, 4);
    s1 += __shfl_xor_sync(0xffffffffu, s1, 4);
    s2 += __shfl_xor_sync(0xffffffffu, s2, 4);
    s3 += __shfl_xor_sync(0xffffffffu, s3, 4);
    s0 += __shfl_xor_sync(0xffffffffu, s0, 2);
    s1 += __shfl_xor_sync(0xffffffffu, s1, 2);
    s2 += __shfl_xor_sync(0xffffffffu, s2, 2);
    s3 += __shfl_xor_sync(0xffffffffu, s3, 2);
    s0 += __shfl_xor_sync(0xffffffffu, s0, 1);
    s1 += __shfl_xor_sync(0xffffffffu, s1, 1);
    s2 += __shfl_xor_sync(0xffffffffu, s2, 1);
    s3 += __shfl_xor_sync(0xffffffffu, s3, 1);

    // Lanes 0..3 of each group store edges eb+0..eb+3.
    float v = s0;
    if (sub == 1) v = s1;
    if (sub == 2) v = s2;
    if (sub == 3) v = s3;

    const int e = e0 + eb + sub;
    if (sub < 4 && e < E) {
        out[e] = __fdividef(1.0f, 1.0f + __expf(-v));
    }
}

extern "C" void kernel_launch(void* const* d_in, const int* in_sizes, int n_in,
                              void* d_out, int out_size)
{
    int E = out_size;  // one score per edge

    const float* x  = nullptr;
    const float* R  = nullptr;
    const void*  ei = nullptr;
    const void*  et = nullptr;
    for (int i = 0; i < n_in; i++) {
        long long sz = in_sizes[i];
        if      (sz == 2LL * E)      ei = d_in[i];
        else if (sz == (long long)E) et = d_in[i];
        else if (sz == 30848LL)      R  = (const float*)d_in[i];
        else                         x  = (const float*)d_in[i];
    }
    if (!x || !R || !ei || !et) {
        x  = (const float*)d_in[0];
        R  = (const float*)d_in[1];
        ei = d_in[2];
        et = d_in[3];
    }

    detect_idx_dtype<<<1, 1>>>(ei);

    int blocks = (E + 127) / 128;
    distmult_kernel<<<blocks, 256>>>(x, R, ei, et, (float*)d_out, E);
}